// round 1
// baseline (speedup 1.0000x reference)
#include <cuda_runtime.h>
#include <cstdint>

// Problem constants
#define BB 64
#define SS 14
#define NSP (SS*SS)      // 196 spatial
#define CC 32
#define NN (NSP*CC)      // 6272
#define OO 10
#define HH 16
#define EPSV 1e-9f
#define NBLK 13          // blocks per batch: 13*512 = 6656 >= 6272
#define CHUNK 512        // n per block (2 per thread, 256 threads)

// Scratch (device globals: allocation-free rule)
__device__ float g_partials[BB * OO * NBLK * 40]; // 33 used per slot
__device__ float g_params[BB * OO * 40];          // [0..15]=mean [16..31]=0.5/var [32]=K0

__device__ __forceinline__ float warp_red(float v) {
    v += __shfl_down_sync(0xffffffffu, v, 16);
    v += __shfl_down_sync(0xffffffffu, v, 8);
    v += __shfl_down_sync(0xffffffffu, v, 4);
    v += __shfl_down_sync(0xffffffffu, v, 2);
    v += __shfl_down_sync(0xffffffffu, v, 1);
    return v;
}

// votes[n,c,o,i,k] = sum_j pose[n,c,i,j] * w[c,o,j,k]  (+ coord at h=0,1)
__device__ __forceinline__ void compute_votes(const float4 P[4], const float4* __restrict__ w_s,
                                              int o, int c, float cr, float cc, float v[16]) {
    const float4 w0 = w_s[(o * 4 + 0) * 32 + c];
    const float4 w1 = w_s[(o * 4 + 1) * 32 + c];
    const float4 w2 = w_s[(o * 4 + 2) * 32 + c];
    const float4 w3 = w_s[(o * 4 + 3) * 32 + c];
#pragma unroll
    for (int i = 0; i < 4; i++) {
        float4 p = P[i];
        v[i * 4 + 0] = fmaf(p.x, w0.x, fmaf(p.y, w1.x, fmaf(p.z, w2.x, p.w * w3.x)));
        v[i * 4 + 1] = fmaf(p.x, w0.y, fmaf(p.y, w1.y, fmaf(p.z, w2.y, p.w * w3.y)));
        v[i * 4 + 2] = fmaf(p.x, w0.z, fmaf(p.y, w1.z, fmaf(p.z, w2.z, p.w * w3.z)));
        v[i * 4 + 3] = fmaf(p.x, w0.w, fmaf(p.y, w1.w, fmaf(p.z, w2.w, p.w * w3.w)));
    }
    v[0] += cr;
    v[1] += cc;
}

template <bool FIRST>
__global__ void __launch_bounds__(256) em_pass_kernel(const float* __restrict__ pose,
                                                      const float* __restrict__ act,
                                                      const float* __restrict__ w) {
    __shared__ float4 w_s[OO * 4 * 32];     // [o][j][c] -> float4 over k, 20KB
    __shared__ float p_s[OO * 36];          // params per o
    __shared__ float rp_s[2][OO][256];      // logap then rr*a, 20KB
    __shared__ float red_s[8][34];

    const int b = blockIdx.y, nb = blockIdx.x;
    const int tid = threadIdx.x, lane = tid & 31, wid = tid >> 5;

    // Stage w: global layout ((c*10+o)*4+j)*4+k -> smem [(o*4+j)*32 + c] (lane-conflict-free)
    const float4* wg4 = reinterpret_cast<const float4*>(w);
    for (int idx = tid; idx < CC * 40; idx += 256) {
        int ci = idx / 40, r = idx % 40;  // r = o*4+j
        w_s[r * 32 + ci] = wg4[idx];
    }
    if (!FIRST) {
        for (int idx = tid; idx < OO * 36; idx += 256) {
            int o = idx / 36, t = idx % 36;
            p_s[idx] = (t < 33) ? g_params[(b * OO + o) * 40 + t] : 0.f;
        }
    }
    __syncthreads();

    // Per-thread data: 2 routing items n
    float4 P[2][4];
    float a[2], crr[2], ccv[2];
    int cw[2];
#pragma unroll
    for (int ln = 0; ln < 2; ln++) {
        int n = nb * CHUNK + ln * 256 + tid;
        bool valid = n < NN;
        int nn = valid ? n : (NN - 1);
        int ns = nn >> 5, ci = nn & 31;
        cw[ln] = ci;
        const float4* pp = reinterpret_cast<const float4*>(pose) +
                           (size_t)((b * NSP + ns) * CC + ci) * 4;
        P[ln][0] = pp[0]; P[ln][1] = pp[1]; P[ln][2] = pp[2]; P[ln][3] = pp[3];
        a[ln] = valid ? act[(size_t)b * NN + n] : 0.f;
        int s1 = ns / SS, s2 = ns % SS;
        crr[ln] = (s1 + 0.5f) * (1.f / SS);
        ccv[ln] = (s2 + 0.5f) * (1.f / SS);
    }

    if (!FIRST) {
        // Pass A: log_ap per (n,o), staged in rp_s (keeps o-loop rolled, no local mem)
        for (int o = 0; o < OO; o++) {
#pragma unroll
            for (int ln = 0; ln < 2; ln++) {
                float v[16];
                compute_votes(P[ln], w_s, o, cw[ln], crr[ln], ccv[ln], v);
                float acc = 0.f;
#pragma unroll
                for (int h = 0; h < 16; h++) {
                    float d = v[h] - p_s[o * 36 + h];
                    acc = fmaf(d * p_s[o * 36 + 16 + h], d, acc);
                }
                rp_s[ln][o][tid] = p_s[o * 36 + 32] - acc;
            }
        }
        // Softmax over o -> rp = rr * a (thread-private smem lane, no sync needed)
#pragma unroll
        for (int ln = 0; ln < 2; ln++) {
            float mx = -3.4e38f;
            for (int o = 0; o < OO; o++) mx = fmaxf(mx, rp_s[ln][o][tid]);
            float s = 0.f;
            for (int o = 0; o < OO; o++) {
                float e = __expf(rp_s[ln][o][tid] - mx);
                rp_s[ln][o][tid] = e;
                s += e;
            }
            float sc = a[ln] / s;
            for (int o = 0; o < OO; o++) rp_s[ln][o][tid] *= sc;
        }
    }

    // Pass B: weighted stats per o, deterministic block reduction
    for (int o = 0; o < OO; o++) {
        float S0 = 0.f, S1[16], S2[16];
#pragma unroll
        for (int h = 0; h < 16; h++) { S1[h] = 0.f; S2[h] = 0.f; }
#pragma unroll
        for (int ln = 0; ln < 2; ln++) {
            float rp = FIRST ? (a[ln] * (1.f / OO)) : rp_s[ln][o][tid];
            float v[16];
            compute_votes(P[ln], w_s, o, cw[ln], crr[ln], ccv[ln], v);
            S0 += rp;
#pragma unroll
            for (int h = 0; h < 16; h++) {
                float t = rp * v[h];
                S1[h] += t;
                S2[h] = fmaf(t, v[h], S2[h]);
            }
        }
        S0 = warp_red(S0);
#pragma unroll
        for (int h = 0; h < 16; h++) { S1[h] = warp_red(S1[h]); S2[h] = warp_red(S2[h]); }
        if (lane == 0) {
            red_s[wid][0] = S0;
#pragma unroll
            for (int h = 0; h < 16; h++) { red_s[wid][1 + h] = S1[h]; red_s[wid][17 + h] = S2[h]; }
        }
        __syncthreads();
        if (tid < 33) {
            float s = red_s[0][tid];
#pragma unroll
            for (int wdx = 1; wdx < 8; wdx++) s += red_s[wdx][tid];
            g_partials[((b * OO + o) * NBLK + nb) * 40 + tid] = s;
        }
        __syncthreads();
    }
}

__global__ void finalize_kernel(const float* __restrict__ beta_a, const float* __restrict__ beta_v,
                                float inv_temp, int is_final, float* __restrict__ out) {
    __shared__ float sums[33];
    const int o = blockIdx.x, b = blockIdx.y, t = threadIdx.x;
    if (t < 33) {
        float s = 0.f;
        for (int nb = 0; nb < NBLK; nb++) s += g_partials[((b * OO + o) * NBLK + nb) * 40 + t];
        sums[t] = s;
    }
    __syncthreads();
    if (t < 16) {
        float S0 = sums[0];
        float S1 = sums[1 + t], S2 = sums[17 + t];
        float inv = 1.f / (S0 + EPSV);
        float mean = S1 * inv;
        float raw = S2 - mean * (2.f * S1 - mean * S0);  // == sum rp*(v-mean)^2 exactly
        float var = fmaxf(raw * inv, 0.f) + EPSV;
        float lv = logf(var);
        float lvs = lv;
        for (int off = 8; off; off >>= 1) lvs += __shfl_down_sync(0x0000ffffu, lvs, off);
        if (is_final) {
            out[((size_t)b * OO + o) * 16 + t] = mean;
        } else {
            g_params[(b * OO + o) * 40 + t] = mean;
            g_params[(b * OO + o) * 40 + 16 + t] = 0.5f / var;
        }
        if (t == 0) {
            float bv = beta_v[o], ba = beta_a[o];
            float cost = S0 * fmaf(0.5f, lvs, 16.f * bv);
            float actj = 1.f / (1.f + expf(-inv_temp * (ba - cost)));
            if (is_final) {
                out[(size_t)BB * OO * 16 + b * OO + o] = actj;
            } else {
                // K0 = log(act+eps) - 0.5*sum_h log(2*pi*var_h)
                g_params[(b * OO + o) * 40 + 32] =
                    logf(actj + EPSV) - 0.5f * (16.f * 1.8378770664093453f + lvs);
            }
        }
    }
}

extern "C" void kernel_launch(void* const* d_in, const int* in_sizes, int n_in,
                              void* d_out, int out_size) {
    const float* pose = (const float*)d_in[0];   // (64,14,14,32,16)
    const float* act  = (const float*)d_in[1];   // (64,14,14,32,1)
    const float* w    = (const float*)d_in[2];   // (1,32,10,4,4)
    const float* ba   = (const float*)d_in[3];   // (1,1,10,1)
    const float* bv   = (const float*)d_in[4];   // (1,1,10,1)
    float* out = (float*)d_out;                  // pose_out (64,10,16) then act_out (64,10)

    dim3 gp(NBLK, BB);
    dim3 gf(OO, BB);
    // it 0: inv_temp = 0.01*(1-0.95^1)
    em_pass_kernel<true><<<gp, 256>>>(pose, act, w);
    finalize_kernel<<<gf, 64>>>(ba, bv, 0.0005f, 0, out);
    // it 1: 0.01*(1-0.95^2)
    em_pass_kernel<false><<<gp, 256>>>(pose, act, w);
    finalize_kernel<<<gf, 64>>>(ba, bv, 0.000975f, 0, out);
    // it 2 (final): 0.01*(1-0.95^3)
    em_pass_kernel<false><<<gp, 256>>>(pose, act, w);
    finalize_kernel<<<gf, 64>>>(ba, bv, 0.00142625f, 1, out);
}

// round 2
// speedup vs baseline: 1.3916x; 1.3916x over previous
#include <cuda_runtime.h>
#include <cstdint>

#define BB 64
#define SS 14
#define NSP (SS*SS)      // 196
#define CC 32
#define NN (NSP*CC)      // 6272
#define OO 10
#define HH 16
#define EPSV 1e-9f
#define NBLK 13          // 13*512 = 6656 >= 6272
#define NW 16            // warps per block
#define NSLOT (NBLK*NW)  // 208 warp-partials per (b,o)

typedef unsigned long long u64;

// Scratch
__device__ float g_partials[BB * OO * NSLOT * 36]; // [slot][36]: 0..15 S1, 16..31 S2, 32 S0
__device__ float g_params[BB * OO * 40];           // 0..15 mean, 16..31 0.5/var, 32 K0

// ---- f32x2 packed helpers ----
__device__ __forceinline__ u64 pk(float lo, float hi) {
    u64 r; asm("mov.b64 %0, {%1,%2};" : "=l"(r) : "f"(lo), "f"(hi)); return r;
}
__device__ __forceinline__ void upk(u64 a, float& lo, float& hi) {
    asm("mov.b64 {%0,%1}, %2;" : "=f"(lo), "=f"(hi) : "l"(a));
}
__device__ __forceinline__ u64 f2fma(u64 a, u64 b, u64 c) {
    u64 d; asm("fma.rn.f32x2 %0, %1, %2, %3;" : "=l"(d) : "l"(a), "l"(b), "l"(c)); return d;
}
__device__ __forceinline__ u64 f2mul(u64 a, u64 b) {
    u64 d; asm("mul.rn.f32x2 %0, %1, %2;" : "=l"(d) : "l"(a), "l"(b)); return d;
}
__device__ __forceinline__ u64 f2add(u64 a, u64 b) {
    u64 d; asm("add.rn.f32x2 %0, %1, %2;" : "=l"(d) : "l"(a), "l"(b)); return d;
}

__device__ __forceinline__ float warp_red(float v) {
    v += __shfl_down_sync(0xffffffffu, v, 16);
    v += __shfl_down_sync(0xffffffffu, v, 8);
    v += __shfl_down_sync(0xffffffffu, v, 4);
    v += __shfl_down_sync(0xffffffffu, v, 2);
    v += __shfl_down_sync(0xffffffffu, v, 1);
    return v;
}

// Distributed butterfly reduce: lane L returns sum over all 32 lanes of vals[L].
__device__ __forceinline__ float bfly32(const float vals[32], int lane) {
    float a16[16];
#pragma unroll
    for (int i = 0; i < 16; i++) {
        float mine = (lane & 16) ? vals[i + 16] : vals[i];
        float give = (lane & 16) ? vals[i] : vals[i + 16];
        a16[i] = mine + __shfl_xor_sync(0xffffffffu, give, 16);
    }
    float a8[8];
#pragma unroll
    for (int i = 0; i < 8; i++) {
        float mine = (lane & 8) ? a16[i + 8] : a16[i];
        float give = (lane & 8) ? a16[i] : a16[i + 8];
        a8[i] = mine + __shfl_xor_sync(0xffffffffu, give, 8);
    }
    float a4[4];
#pragma unroll
    for (int i = 0; i < 4; i++) {
        float mine = (lane & 4) ? a8[i + 4] : a8[i];
        float give = (lane & 4) ? a8[i] : a8[i + 4];
        a4[i] = mine + __shfl_xor_sync(0xffffffffu, give, 4);
    }
    float a2[2];
#pragma unroll
    for (int i = 0; i < 2; i++) {
        float mine = (lane & 2) ? a2[0] * 0.f + a4[i + 2] : a4[i]; // avoid uninit warning
        mine = (lane & 2) ? a4[i + 2] : a4[i];
        float give = (lane & 2) ? a4[i] : a4[i + 2];
        a2[i] = mine + __shfl_xor_sync(0xffffffffu, give, 2);
    }
    float mine = (lane & 1) ? a2[1] : a2[0];
    float give = (lane & 1) ? a2[0] : a2[1];
    return mine + __shfl_xor_sync(0xffffffffu, give, 1);
}

template <bool FIRST>
__global__ void __launch_bounds__(512) em_pass_kernel(const float* __restrict__ pose,
                                                      const float* __restrict__ act,
                                                      const float* __restrict__ w) {
    __shared__ __align__(16) u64 w_s[OO * 4 * 2 * 32];  // [(o*4+j)*2+half][c], 20KB
    __shared__ __align__(16) float p_s[OO * 36];        // -mean[16], hv[16], K0
    __shared__ float rp_s[OO][512];                     // 20KB

    const int b = blockIdx.y, nb = blockIdx.x;
    const int tid = threadIdx.x, lane = tid & 31, wid = tid >> 5;

    // Stage w: global (c,o,j,k) float4 over k -> packed pairs [(o*4+j)*2+half][c]
    const float4* wg4 = reinterpret_cast<const float4*>(w);
    for (int idx = tid; idx < CC * 40; idx += 512) {
        int ci = idx / 40, r = idx % 40;  // r = o*4+j
        float4 t = wg4[idx];
        w_s[(r * 2 + 0) * 32 + ci] = pk(t.x, t.y);
        w_s[(r * 2 + 1) * 32 + ci] = pk(t.z, t.w);
    }
    if (!FIRST) {
        for (int idx = tid; idx < OO * 36; idx += 512) {
            int o = idx / 36, t = idx % 36;
            float v = (t < 33) ? g_params[(b * OO + o) * 40 + t] : 0.f;
            if (t < 16) v = -v;  // store negated mean
            p_s[idx] = v;
        }
    }
    __syncthreads();

    // Per-thread item
    const int n = nb * 512 + tid;
    const bool valid = n < NN;
    const int nn = valid ? n : (NN - 1);
    const int ns = nn >> 5, c = nn & 31;
    const float4* pp = reinterpret_cast<const float4*>(pose) +
                       (size_t)((b * NSP + ns) * CC + c) * 4;
    float4 P0 = pp[0], P1 = pp[1], P2 = pp[2], P3 = pp[3];
    const float a = valid ? act[(size_t)b * NN + n] : 0.f;
    const int s1 = ns / SS, s2 = ns % SS;
    const u64 cpair = pk((s1 + 0.5f) * (1.f / SS), (s2 + 0.5f) * (1.f / SS));

    // Broadcast pose pairs
    u64 Pb[16];
    Pb[0] = pk(P0.x, P0.x); Pb[1] = pk(P0.y, P0.y); Pb[2] = pk(P0.z, P0.z); Pb[3] = pk(P0.w, P0.w);
    Pb[4] = pk(P1.x, P1.x); Pb[5] = pk(P1.y, P1.y); Pb[6] = pk(P1.z, P1.z); Pb[7] = pk(P1.w, P1.w);
    Pb[8] = pk(P2.x, P2.x); Pb[9] = pk(P2.y, P2.y); Pb[10] = pk(P2.z, P2.z); Pb[11] = pk(P2.w, P2.w);
    Pb[12] = pk(P3.x, P3.x); Pb[13] = pk(P3.y, P3.y); Pb[14] = pk(P3.z, P3.z); Pb[15] = pk(P3.w, P3.w);

    // votes for output capsule o -> 8 packed pairs (h = 2q, 2q+1)
    auto votes = [&](int o, u64 v[8]) {
        const u64* wp = &w_s[o * 256 + c];
#pragma unroll
        for (int i = 0; i < 4; i++) {
            u64 acc0 = f2mul(Pb[i * 4 + 3], wp[6 * 32]);
            acc0 = f2fma(Pb[i * 4 + 2], wp[4 * 32], acc0);
            acc0 = f2fma(Pb[i * 4 + 1], wp[2 * 32], acc0);
            acc0 = f2fma(Pb[i * 4 + 0], wp[0], acc0);
            u64 acc1 = f2mul(Pb[i * 4 + 3], wp[7 * 32]);
            acc1 = f2fma(Pb[i * 4 + 2], wp[5 * 32], acc1);
            acc1 = f2fma(Pb[i * 4 + 1], wp[3 * 32], acc1);
            acc1 = f2fma(Pb[i * 4 + 0], wp[1 * 32], acc1);
            v[i * 2 + 0] = acc0;
            v[i * 2 + 1] = acc1;
        }
        v[0] = f2add(v[0], cpair);  // coords on h=0,1
    };

    if (!FIRST) {
        // Pass A: log_ap per o
#pragma unroll 1
        for (int o = 0; o < OO; o++) {
            u64 v[8];
            votes(o, v);
            const u64* mp = reinterpret_cast<const u64*>(p_s + o * 36);
            u64 ap = 0;
#pragma unroll
            for (int q = 0; q < 8; q++) {
                u64 d = f2add(v[q], mp[q]);            // v - mean
                ap = f2fma(f2mul(d, d), mp[8 + q], ap); // += d^2 * (0.5/var)
            }
            float l, h;
            upk(ap, l, h);
            rp_s[o][tid] = p_s[o * 36 + 32] - (l + h);
        }
        // Softmax over o, scale by a (thread-private smem column)
        float mx = -3.4e38f;
#pragma unroll
        for (int o = 0; o < OO; o++) mx = fmaxf(mx, rp_s[o][tid]);
        float s = 0.f;
#pragma unroll
        for (int o = 0; o < OO; o++) {
            float e = __expf(rp_s[o][tid] - mx);
            rp_s[o][tid] = e;
            s += e;
        }
        float sc = a / s;
#pragma unroll
        for (int o = 0; o < OO; o++) rp_s[o][tid] *= sc;
    }

    // Pass B: weighted moments + warp butterfly reduce, straight to global
#pragma unroll 1
    for (int o = 0; o < OO; o++) {
        u64 v[8];
        votes(o, v);
        float rp = FIRST ? a * (1.f / OO) : rp_s[o][tid];
        u64 rpp = pk(rp, rp);
        float vals[32];
#pragma unroll
        for (int q = 0; q < 8; q++) {
            u64 t1 = f2mul(rpp, v[q]);            // rp*v  -> S1 pair
            u64 t2 = f2mul(t1, v[q]);             // rp*v^2 -> S2 pair
            upk(t1, vals[2 * q], vals[2 * q + 1]);
            upk(t2, vals[16 + 2 * q], vals[17 + 2 * q]);
        }
        float r = bfly32(vals, lane);
        float S0r = warp_red(rp);
        int base = (((b * OO + o) * NBLK + nb) * NW + wid) * 36;
        g_partials[base + lane] = r;
        if (lane == 0) g_partials[base + 32] = S0r;
    }
}

__global__ void __launch_bounds__(144) finalize_kernel(const float* __restrict__ beta_a,
                                                       const float* __restrict__ beta_v,
                                                       float inv_temp, int is_final,
                                                       float* __restrict__ out) {
    __shared__ float part[4][36];
    __shared__ float sums[36];
    const int o = blockIdx.x, b = blockIdx.y, tid = threadIdx.x;
    const int g = tid / 36, t = tid % 36;
    const size_t base = (size_t)(b * OO + o) * NSLOT * 36;
    float s = 0.f;
#pragma unroll 4
    for (int k = g * (NSLOT / 4); k < (g + 1) * (NSLOT / 4); k++)
        s += g_partials[base + (size_t)k * 36 + t];
    part[g][t] = s;
    __syncthreads();
    if (tid < 36) sums[tid] = part[0][tid] + part[1][tid] + part[2][tid] + part[3][tid];
    __syncthreads();
    if (tid < 16) {
        float S0 = sums[32];
        float S1 = sums[tid], S2 = sums[16 + tid];
        float inv = 1.f / (S0 + EPSV);
        float mean = S1 * inv;
        float raw = S2 - mean * (2.f * S1 - mean * S0);  // == sum rp*(v-mean)^2 exactly
        float var = fmaxf(raw * inv, 0.f) + EPSV;
        float lv = logf(var);
        float lvs = lv;
        for (int off = 8; off; off >>= 1) lvs += __shfl_down_sync(0x0000ffffu, lvs, off);
        if (is_final) {
            out[((size_t)b * OO + o) * 16 + tid] = mean;
        } else {
            g_params[(b * OO + o) * 40 + tid] = mean;
            g_params[(b * OO + o) * 40 + 16 + tid] = 0.5f / var;
        }
        if (tid == 0) {
            float bv = beta_v[o], ba = beta_a[o];
            float cost = S0 * fmaf(0.5f, lvs, 16.f * bv);
            float actj = 1.f / (1.f + expf(-inv_temp * (ba - cost)));
            if (is_final) {
                out[(size_t)BB * OO * 16 + b * OO + o] = actj;
            } else {
                // K0 = log(act+eps) - 0.5*sum_h log(2*pi*var_h)
                g_params[(b * OO + o) * 40 + 32] =
                    logf(actj + EPSV) - 0.5f * (16.f * 1.8378770664093453f + lvs);
            }
        }
    }
}

extern "C" void kernel_launch(void* const* d_in, const int* in_sizes, int n_in,
                              void* d_out, int out_size) {
    const float* pose = (const float*)d_in[0];
    const float* act  = (const float*)d_in[1];
    const float* w    = (const float*)d_in[2];
    const float* ba   = (const float*)d_in[3];
    const float* bv   = (const float*)d_in[4];
    float* out = (float*)d_out;

    dim3 gp(NBLK, BB);
    dim3 gf(OO, BB);
    em_pass_kernel<true><<<gp, 512>>>(pose, act, w);
    finalize_kernel<<<gf, 144>>>(ba, bv, 0.0005f, 0, out);
    em_pass_kernel<false><<<gp, 512>>>(pose, act, w);
    finalize_kernel<<<gf, 144>>>(ba, bv, 0.000975f, 0, out);
    em_pass_kernel<false><<<gp, 512>>>(pose, act, w);
    finalize_kernel<<<gf, 144>>>(ba, bv, 0.00142625f, 1, out);
}

// round 3
// speedup vs baseline: 1.4145x; 1.0164x over previous
#include <cuda_runtime.h>
#include <cstdint>

#define BB 64
#define SS 14
#define NSP (SS*SS)      // 196
#define CC 32
#define NN (NSP*CC)      // 6272
#define OO 10
#define HH 16
#define EPSV 1e-9f
#define NBLK 13          // 13*512 = 6656 >= 6272
#define NW 16            // warps per block

typedef unsigned long long u64;

// Scratch
__device__ float g_partials[BB * OO * NBLK * 36]; // per-(b,o,block): 0..15 S1, 16..31 S2, 32 S0
__device__ float g_params[BB * OO * 40];          // 0..15 mean, 16..31 0.5/var, 32 K0

// ---- f32x2 packed helpers ----
__device__ __forceinline__ u64 pk(float lo, float hi) {
    u64 r; asm("mov.b64 %0, {%1,%2};" : "=l"(r) : "f"(lo), "f"(hi)); return r;
}
__device__ __forceinline__ void upk(u64 a, float& lo, float& hi) {
    asm("mov.b64 {%0,%1}, %2;" : "=f"(lo), "=f"(hi) : "l"(a));
}
__device__ __forceinline__ u64 f2fma(u64 a, u64 b, u64 c) {
    u64 d; asm("fma.rn.f32x2 %0, %1, %2, %3;" : "=l"(d) : "l"(a), "l"(b), "l"(c)); return d;
}
__device__ __forceinline__ u64 f2mul(u64 a, u64 b) {
    u64 d; asm("mul.rn.f32x2 %0, %1, %2;" : "=l"(d) : "l"(a), "l"(b)); return d;
}
__device__ __forceinline__ u64 f2add(u64 a, u64 b) {
    u64 d; asm("add.rn.f32x2 %0, %1, %2;" : "=l"(d) : "l"(a), "l"(b)); return d;
}

__device__ __forceinline__ float warp_red(float v) {
    v += __shfl_down_sync(0xffffffffu, v, 16);
    v += __shfl_down_sync(0xffffffffu, v, 8);
    v += __shfl_down_sync(0xffffffffu, v, 4);
    v += __shfl_down_sync(0xffffffffu, v, 2);
    v += __shfl_down_sync(0xffffffffu, v, 1);
    return v;
}

// Butterfly stages 8..1 on a 16-value distributed set.
// On entry lane L's a16[i] holds partial of logical value (L&16 ? 16+i : i).
// On exit lane L holds total of logical value L.
__device__ __forceinline__ float bfly16_tail(float a16[16], int lane) {
    float a8[8];
#pragma unroll
    for (int i = 0; i < 8; i++) {
        float mine = (lane & 8) ? a16[i + 8] : a16[i];
        float give = (lane & 8) ? a16[i] : a16[i + 8];
        a8[i] = mine + __shfl_xor_sync(0xffffffffu, give, 8);
    }
    float a4[4];
#pragma unroll
    for (int i = 0; i < 4; i++) {
        float mine = (lane & 4) ? a8[i + 4] : a8[i];
        float give = (lane & 4) ? a8[i] : a8[i + 4];
        a4[i] = mine + __shfl_xor_sync(0xffffffffu, give, 4);
    }
    float a2[2];
#pragma unroll
    for (int i = 0; i < 2; i++) {
        float mine = (lane & 2) ? a4[i + 2] : a4[i];
        float give = (lane & 2) ? a4[i] : a4[i + 2];
        a2[i] = mine + __shfl_xor_sync(0xffffffffu, give, 2);
    }
    float mine = (lane & 1) ? a2[1] : a2[0];
    float give = (lane & 1) ? a2[0] : a2[1];
    return mine + __shfl_xor_sync(0xffffffffu, give, 1);
}

template <bool FIRST>
__global__ void __launch_bounds__(512) em_pass_kernel(const float* __restrict__ pose,
                                                      const float* __restrict__ act,
                                                      const float* __restrict__ w) {
    __shared__ __align__(16) u64 w_s[OO * 4 * 2 * 32];  // [(o*4+j)*2+half][c], 20KB
    __shared__ __align__(16) float p_s[OO * 36];        // -mean[16], 0.5/var[16], K0
    __shared__ float rp_s[OO][512];                     // 20KB
    __shared__ float red_s[NW][40];                     // 2.5KB block-reduce buffer

    const int b = blockIdx.y, nb = blockIdx.x;
    const int tid = threadIdx.x, lane = tid & 31, wid = tid >> 5;

    // Stage w: global (c,o,j,k) float4 over k -> packed pairs [(o*4+j)*2+half][c]
    const float4* wg4 = reinterpret_cast<const float4*>(w);
    for (int idx = tid; idx < CC * 40; idx += 512) {
        int ci = idx / 40, r = idx % 40;  // r = o*4+j
        float4 t = wg4[idx];
        w_s[(r * 2 + 0) * 32 + ci] = pk(t.x, t.y);
        w_s[(r * 2 + 1) * 32 + ci] = pk(t.z, t.w);
    }
    if (!FIRST) {
        for (int idx = tid; idx < OO * 36; idx += 512) {
            int o = idx / 36, t = idx % 36;
            float v = (t < 33) ? g_params[(b * OO + o) * 40 + t] : 0.f;
            if (t < 16) v = -v;  // store negated mean
            p_s[idx] = v;
        }
    }
    __syncthreads();

    // Per-thread item
    const int n = nb * 512 + tid;
    const bool valid = n < NN;
    const int nn = valid ? n : (NN - 1);
    const int ns = nn >> 5, c = nn & 31;  // c == lane (512 % 32 == 0)
    const float4* pp = reinterpret_cast<const float4*>(pose) +
                       (size_t)((b * NSP + ns) * CC + c) * 4;
    float4 P0 = pp[0], P1 = pp[1], P2 = pp[2], P3 = pp[3];
    const float a = valid ? act[(size_t)b * NN + n] : 0.f;
    const int s1 = ns / SS, s2 = ns % SS;
    const u64 cpair = pk((s1 + 0.5f) * (1.f / SS), (s2 + 0.5f) * (1.f / SS));

    // Broadcast pose pairs
    u64 Pb[16];
    Pb[0] = pk(P0.x, P0.x); Pb[1] = pk(P0.y, P0.y); Pb[2] = pk(P0.z, P0.z); Pb[3] = pk(P0.w, P0.w);
    Pb[4] = pk(P1.x, P1.x); Pb[5] = pk(P1.y, P1.y); Pb[6] = pk(P1.z, P1.z); Pb[7] = pk(P1.w, P1.w);
    Pb[8] = pk(P2.x, P2.x); Pb[9] = pk(P2.y, P2.y); Pb[10] = pk(P2.z, P2.z); Pb[11] = pk(P2.w, P2.w);
    Pb[12] = pk(P3.x, P3.x); Pb[13] = pk(P3.y, P3.y); Pb[14] = pk(P3.z, P3.z); Pb[15] = pk(P3.w, P3.w);

    // votes for output capsule o -> 8 packed pairs (h = 2q, 2q+1)
    auto votes = [&](int o, u64 v[8]) {
        const u64* wp = &w_s[o * 256 + c];
#pragma unroll
        for (int i = 0; i < 4; i++) {
            u64 acc0 = f2mul(Pb[i * 4 + 3], wp[6 * 32]);
            acc0 = f2fma(Pb[i * 4 + 2], wp[4 * 32], acc0);
            acc0 = f2fma(Pb[i * 4 + 1], wp[2 * 32], acc0);
            acc0 = f2fma(Pb[i * 4 + 0], wp[0], acc0);
            u64 acc1 = f2mul(Pb[i * 4 + 3], wp[7 * 32]);
            acc1 = f2fma(Pb[i * 4 + 2], wp[5 * 32], acc1);
            acc1 = f2fma(Pb[i * 4 + 1], wp[3 * 32], acc1);
            acc1 = f2fma(Pb[i * 4 + 0], wp[1 * 32], acc1);
            v[i * 2 + 0] = acc0;
            v[i * 2 + 1] = acc1;
        }
        v[0] = f2add(v[0], cpair);  // coords on h=0,1
    };

    if (!FIRST) {
        // Pass A: log_ap per o
#pragma unroll 1
        for (int o = 0; o < OO; o++) {
            u64 v[8];
            votes(o, v);
            const u64* mp = reinterpret_cast<const u64*>(p_s + o * 36);
            u64 ap = 0;
#pragma unroll
            for (int q = 0; q < 8; q++) {
                u64 d = f2add(v[q], mp[q]);             // v - mean
                ap = f2fma(f2mul(d, d), mp[8 + q], ap);  // += d^2 * (0.5/var)
            }
            float l, h;
            upk(ap, l, h);
            rp_s[o][tid] = p_s[o * 36 + 32] - (l + h);
        }
        // Softmax over o, scale by a (thread-private smem column)
        float mx = -3.4e38f;
#pragma unroll
        for (int o = 0; o < OO; o++) mx = fmaxf(mx, rp_s[o][tid]);
        float s = 0.f;
#pragma unroll
        for (int o = 0; o < OO; o++) {
            float e = __expf(rp_s[o][tid] - mx);
            rp_s[o][tid] = e;
            s += e;
        }
        float sc = a / s;
#pragma unroll
        for (int o = 0; o < OO; o++) rp_s[o][tid] *= sc;
    }

    // Pass B: weighted moments; butterfly stage-1 fused into the q-loop
    // (S1 pair exchanges with S2 pair), then block-level fold via smem.
#pragma unroll 1
    for (int o = 0; o < OO; o++) {
        u64 v[8];
        votes(o, v);
        float rp = FIRST ? a * (1.f / OO) : rp_s[o][tid];
        u64 rpp = pk(rp, rp);
        float a16[16];
#pragma unroll
        for (int q = 0; q < 8; q++) {
            u64 t1 = f2mul(rpp, v[q]);   // (S1[2q], S1[2q+1])
            u64 t2 = f2mul(t1, v[q]);    // (S2[2q], S2[2q+1])
            float s1l, s1h, s2l, s2h;
            upk(t1, s1l, s1h);
            upk(t2, s2l, s2h);
            // stage 16: logical value i pairs with i+16 (S1[j] <-> S2[j])
            float ml = (lane & 16) ? s2l : s1l;
            float gl = (lane & 16) ? s1l : s2l;
            a16[2 * q] = ml + __shfl_xor_sync(0xffffffffu, gl, 16);
            float mh = (lane & 16) ? s2h : s1h;
            float gh = (lane & 16) ? s1h : s2h;
            a16[2 * q + 1] = mh + __shfl_xor_sync(0xffffffffu, gh, 16);
        }
        float r = bfly16_tail(a16, lane);   // lane L holds warp total of S1S2[L]
        float S0r = warp_red(rp);
        red_s[wid][lane] = r;
        if (lane == 0) red_s[wid][32] = S0r;
        __syncthreads();
        if (tid < 33) {
            float s = red_s[0][tid];
#pragma unroll
            for (int wdx = 1; wdx < NW; wdx++) s += red_s[wdx][tid];
            g_partials[((b * OO + o) * NBLK + nb) * 36 + tid] = s;
        }
        __syncthreads();
    }
}

__global__ void __launch_bounds__(64) finalize_kernel(const float* __restrict__ beta_a,
                                                      const float* __restrict__ beta_v,
                                                      float inv_temp, int is_final,
                                                      float* __restrict__ out) {
    __shared__ float sums[36];
    const int o = blockIdx.x, b = blockIdx.y, t = threadIdx.x;
    if (t < 33) {
        const size_t base = (size_t)(b * OO + o) * NBLK * 36;
        float s = 0.f;
#pragma unroll
        for (int k = 0; k < NBLK; k++) s += g_partials[base + k * 36 + t];
        sums[t] = s;
    }
    __syncthreads();
    if (t < 16) {
        float S0 = sums[32];
        float S1 = sums[t], S2 = sums[16 + t];
        float inv = 1.f / (S0 + EPSV);
        float mean = S1 * inv;
        float raw = S2 - mean * (2.f * S1 - mean * S0);  // == sum rp*(v-mean)^2 exactly
        float var = fmaxf(raw * inv, 0.f) + EPSV;
        float lv = logf(var);
        float lvs = lv;
        for (int off = 8; off; off >>= 1) lvs += __shfl_down_sync(0x0000ffffu, lvs, off);
        if (is_final) {
            out[((size_t)b * OO + o) * 16 + t] = mean;
        } else {
            g_params[(b * OO + o) * 40 + t] = mean;
            g_params[(b * OO + o) * 40 + 16 + t] = 0.5f / var;
        }
        if (t == 0) {
            float bv = beta_v[o], ba = beta_a[o];
            float cost = S0 * fmaf(0.5f, lvs, 16.f * bv);
            float actj = 1.f / (1.f + expf(-inv_temp * (ba - cost)));
            if (is_final) {
                out[(size_t)BB * OO * 16 + b * OO + o] = actj;
            } else {
                // K0 = log(act+eps) - 0.5*sum_h log(2*pi*var_h)
                g_params[(b * OO + o) * 40 + 32] =
                    logf(actj + EPSV) - 0.5f * (16.f * 1.8378770664093453f + lvs);
            }
        }
    }
}

extern "C" void kernel_launch(void* const* d_in, const int* in_sizes, int n_in,
                              void* d_out, int out_size) {
    const float* pose = (const float*)d_in[0];
    const float* act  = (const float*)d_in[1];
    const float* w    = (const float*)d_in[2];
    const float* ba   = (const float*)d_in[3];
    const float* bv   = (const float*)d_in[4];
    float* out = (float*)d_out;

    dim3 gp(NBLK, BB);
    dim3 gf(OO, BB);
    em_pass_kernel<true><<<gp, 512>>>(pose, act, w);
    finalize_kernel<<<gf, 64>>>(ba, bv, 0.0005f, 0, out);
    em_pass_kernel<false><<<gp, 512>>>(pose, act, w);
    finalize_kernel<<<gf, 64>>>(ba, bv, 0.000975f, 0, out);
    em_pass_kernel<false><<<gp, 512>>>(pose, act, w);
    finalize_kernel<<<gf, 64>>>(ba, bv, 0.00142625f, 1, out);
}

// round 4
// speedup vs baseline: 1.5559x; 1.1000x over previous
#include <cuda_runtime.h>
#include <cstdint>

#define BB 64
#define SS 14
#define NSP (SS*SS)      // 196
#define CC 32
#define NN (NSP*CC)      // 6272
#define OO 10
#define HH 16
#define EPSV 1e-9f
#define NBLK 25          // 25*256 = 6400 >= 6272
#define NW 8             // warps per block

typedef unsigned long long u64;

// Scratch
__device__ float g_partials[BB * OO * NBLK * 36]; // per-(b,o,block): 0..15 S1, 16..31 S2, 32 S0
__device__ float g_params[BB * OO * 40];          // 0..15 mean, 16..31 0.5/var, 32 K0

// ---- f32x2 packed helpers ----
__device__ __forceinline__ u64 pk(float lo, float hi) {
    u64 r; asm("mov.b64 %0, {%1,%2};" : "=l"(r) : "f"(lo), "f"(hi)); return r;
}
__device__ __forceinline__ void upk(u64 a, float& lo, float& hi) {
    asm("mov.b64 {%0,%1}, %2;" : "=f"(lo), "=f"(hi) : "l"(a));
}
__device__ __forceinline__ u64 f2fma(u64 a, u64 b, u64 c) {
    u64 d; asm("fma.rn.f32x2 %0, %1, %2, %3;" : "=l"(d) : "l"(a), "l"(b), "l"(c)); return d;
}
__device__ __forceinline__ u64 f2mul(u64 a, u64 b) {
    u64 d; asm("mul.rn.f32x2 %0, %1, %2;" : "=l"(d) : "l"(a), "l"(b)); return d;
}
__device__ __forceinline__ u64 f2add(u64 a, u64 b) {
    u64 d; asm("add.rn.f32x2 %0, %1, %2;" : "=l"(d) : "l"(a), "l"(b)); return d;
}

// Butterfly stages 8..1 on a 16-value distributed set (entry: lane bit4 = value bit3).
__device__ __forceinline__ float bfly16_tail(float a16[16], int lane) {
    float a8[8];
#pragma unroll
    for (int i = 0; i < 8; i++) {
        float mine = (lane & 8) ? a16[i + 8] : a16[i];
        float give = (lane & 8) ? a16[i] : a16[i + 8];
        a8[i] = mine + __shfl_xor_sync(0xffffffffu, give, 8);
    }
    float a4[4];
#pragma unroll
    for (int i = 0; i < 4; i++) {
        float mine = (lane & 4) ? a8[i + 4] : a8[i];
        float give = (lane & 4) ? a8[i] : a8[i + 4];
        a4[i] = mine + __shfl_xor_sync(0xffffffffu, give, 4);
    }
    float a2[2];
#pragma unroll
    for (int i = 0; i < 2; i++) {
        float mine = (lane & 2) ? a4[i + 2] : a4[i];
        float give = (lane & 2) ? a4[i] : a4[i + 2];
        a2[i] = mine + __shfl_xor_sync(0xffffffffu, give, 2);
    }
    float mine = (lane & 1) ? a2[1] : a2[0];
    float give = (lane & 1) ? a2[0] : a2[1];
    return mine + __shfl_xor_sync(0xffffffffu, give, 1);
}

// Distributed reduce of 16 values over 32 lanes: returns (on every lane) the
// total of value index (lane>>1)&15. 16 shuffles.
__device__ __forceinline__ float bfly16_full(const float val[16], int lane) {
    float v8[8];
#pragma unroll
    for (int i = 0; i < 8; i++) {
        float mine = (lane & 16) ? val[i + 8] : val[i];
        float give = (lane & 16) ? val[i] : val[i + 8];
        v8[i] = mine + __shfl_xor_sync(0xffffffffu, give, 16);
    }
    float v4[4];
#pragma unroll
    for (int i = 0; i < 4; i++) {
        float mine = (lane & 8) ? v8[i + 4] : v8[i];
        float give = (lane & 8) ? v8[i] : v8[i + 4];
        v4[i] = mine + __shfl_xor_sync(0xffffffffu, give, 8);
    }
    float v2[2];
#pragma unroll
    for (int i = 0; i < 2; i++) {
        float mine = (lane & 4) ? v4[i + 2] : v4[i];
        float give = (lane & 4) ? v4[i] : v4[i + 2];
        v2[i] = mine + __shfl_xor_sync(0xffffffffu, give, 4);
    }
    float mine = (lane & 2) ? v2[1] : v2[0];
    float give = (lane & 2) ? v2[0] : v2[1];
    float v1 = mine + __shfl_xor_sync(0xffffffffu, give, 2);
    return v1 + __shfl_xor_sync(0xffffffffu, v1, 1);
}

template <bool FIRST>
__global__ void __launch_bounds__(256) em_pass_kernel(const float* __restrict__ pose,
                                                      const float* __restrict__ act,
                                                      const float* __restrict__ w) {
    __shared__ __align__(16) u64 w_s[OO * 4 * 32 * 2];  // [(o*4+j)*32+c] -> 2 adjacent u64, 10KB
    __shared__ __align__(16) float p_s[OO * 36];        // -mean[16], 0.5/var[16], K0
    __shared__ float red_s[NW][OO][32];                 // 10KB per-warp S1S2 partials
    __shared__ float red0_s[NW][16];                    // S0 partials

    const int b = blockIdx.y, nb = blockIdx.x;
    const int tid = threadIdx.x, lane = tid & 31, wid = tid >> 5;

    // Stage w: global (c,o,j,k) float4 over k -> adjacent packed pairs at [(o*4+j)*32+c]
    const float4* wg4 = reinterpret_cast<const float4*>(w);
    for (int idx = tid; idx < CC * 40; idx += 256) {
        int ci = idx / 40, r = idx % 40;  // r = o*4+j
        float4 t = wg4[idx];
        w_s[((r * 32) + ci) * 2 + 0] = pk(t.x, t.y);
        w_s[((r * 32) + ci) * 2 + 1] = pk(t.z, t.w);
    }
    if (!FIRST) {
        for (int idx = tid; idx < OO * 36; idx += 256) {
            int o = idx / 36, t = idx % 36;
            float v = (t < 33) ? g_params[(b * OO + o) * 40 + t] : 0.f;
            if (t < 16) v = -v;  // store negated mean
            p_s[idx] = v;
        }
    }
    __syncthreads();

    // Per-thread item
    const int n = nb * 256 + tid;
    const bool valid = n < NN;
    const int nn = valid ? n : (NN - 1);
    const int ns = nn >> 5, c = nn & 31;  // c == lane
    const float4* pp = reinterpret_cast<const float4*>(pose) +
                       (size_t)((b * NSP + ns) * CC + c) * 4;
    float4 P0 = pp[0], P1 = pp[1], P2 = pp[2], P3 = pp[3];
    const float a = valid ? act[(size_t)b * NN + n] : 0.f;
    const int s1 = ns / SS, s2 = ns % SS;
    const u64 cpair = pk((s1 + 0.5f) * (1.f / SS), (s2 + 0.5f) * (1.f / SS));

    // Broadcast pose pairs
    u64 Pb[16];
    Pb[0] = pk(P0.x, P0.x); Pb[1] = pk(P0.y, P0.y); Pb[2] = pk(P0.z, P0.z); Pb[3] = pk(P0.w, P0.w);
    Pb[4] = pk(P1.x, P1.x); Pb[5] = pk(P1.y, P1.y); Pb[6] = pk(P1.z, P1.z); Pb[7] = pk(P1.w, P1.w);
    Pb[8] = pk(P2.x, P2.x); Pb[9] = pk(P2.y, P2.y); Pb[10] = pk(P2.z, P2.z); Pb[11] = pk(P2.w, P2.w);
    Pb[12] = pk(P3.x, P3.x); Pb[13] = pk(P3.y, P3.y); Pb[14] = pk(P3.z, P3.z); Pb[15] = pk(P3.w, P3.w);

    const ulonglong2* wq = reinterpret_cast<const ulonglong2*>(w_s);

    // votes for output capsule o -> 8 packed pairs (h = 2q, 2q+1)
    auto votes = [&](int o, u64 v[8]) {
        const ulonglong2* wp = wq + o * 128 + c;  // [j*32]
        ulonglong2 W0 = wp[0], W1 = wp[32], W2 = wp[64], W3 = wp[96];
#pragma unroll
        for (int i = 0; i < 4; i++) {
            u64 acc0 = f2mul(Pb[i * 4 + 3], W3.x);
            acc0 = f2fma(Pb[i * 4 + 2], W2.x, acc0);
            acc0 = f2fma(Pb[i * 4 + 1], W1.x, acc0);
            acc0 = f2fma(Pb[i * 4 + 0], W0.x, acc0);
            u64 acc1 = f2mul(Pb[i * 4 + 3], W3.y);
            acc1 = f2fma(Pb[i * 4 + 2], W2.y, acc1);
            acc1 = f2fma(Pb[i * 4 + 1], W1.y, acc1);
            acc1 = f2fma(Pb[i * 4 + 0], W0.y, acc1);
            v[i * 2 + 0] = acc0;
            v[i * 2 + 1] = acc1;
        }
        v[0] = f2add(v[0], cpair);  // coords on h=0,1
    };

    float rp[OO];
    if (FIRST) {
#pragma unroll
        for (int o = 0; o < OO; o++) rp[o] = a * (1.f / OO);
    } else {
        // Pass A: log_ap per o, all in registers
#pragma unroll
        for (int o = 0; o < OO; o++) {
            u64 v[8];
            votes(o, v);
            const u64* mp = reinterpret_cast<const u64*>(p_s + o * 36);
            u64 ap = 0;
#pragma unroll
            for (int q = 0; q < 8; q++) {
                u64 d = f2add(v[q], mp[q]);              // v - mean
                ap = f2fma(f2mul(d, d), mp[8 + q], ap);  // += d^2 * (0.5/var)
            }
            float l, h;
            upk(ap, l, h);
            rp[o] = p_s[o * 36 + 32] - (l + h);
        }
        // Softmax over o (registers)
        float mx = rp[0];
#pragma unroll
        for (int o = 1; o < OO; o++) mx = fmaxf(mx, rp[o]);
        float s = 0.f;
#pragma unroll
        for (int o = 0; o < OO; o++) {
            rp[o] = __expf(rp[o] - mx);
            s += rp[o];
        }
        float sc = a / s;
#pragma unroll
        for (int o = 0; o < OO; o++) rp[o] *= sc;
    }

    // Pass B: weighted moments; butterfly stage-16 fused into the q-loop
#pragma unroll
    for (int o = 0; o < OO; o++) {
        u64 v[8];
        votes(o, v);
        u64 rpp = pk(rp[o], rp[o]);
        float a16[16];
#pragma unroll
        for (int q = 0; q < 8; q++) {
            u64 t1 = f2mul(rpp, v[q]);   // (S1[2q], S1[2q+1])
            u64 t2 = f2mul(t1, v[q]);    // (S2[2q], S2[2q+1])
            float s1l, s1h, s2l, s2h;
            upk(t1, s1l, s1h);
            upk(t2, s2l, s2h);
            float ml = (lane & 16) ? s2l : s1l;
            float gl = (lane & 16) ? s1l : s2l;
            a16[2 * q] = ml + __shfl_xor_sync(0xffffffffu, gl, 16);
            float mh = (lane & 16) ? s2h : s1h;
            float gh = (lane & 16) ? s1h : s2h;
            a16[2 * q + 1] = mh + __shfl_xor_sync(0xffffffffu, gh, 16);
        }
        red_s[wid][o][lane] = bfly16_tail(a16, lane);
    }
    // S0 for all o: one distributed 16-value reduce (lane L holds S0[L>>1])
    {
        float val[16];
#pragma unroll
        for (int i = 0; i < 16; i++) val[i] = (i < OO) ? rp[i] : 0.f;
        float s0 = bfly16_full(val, lane);
        int o = lane >> 1;
        if (!(lane & 1) && o < OO) red0_s[wid][o] = s0;
    }
    __syncthreads();

    // Single block-level fold: 330 outputs (10 o x 33)
    for (int it = tid; it < OO * 33; it += 256) {
        int o = it / 33, t = it % 33;
        float s = 0.f;
#pragma unroll
        for (int wdx = 0; wdx < NW; wdx++)
            s += (t < 32) ? red_s[wdx][o][t] : red0_s[wdx][o];
        g_partials[((b * OO + o) * NBLK + nb) * 36 + t] = s;
    }
}

__global__ void __launch_bounds__(64) finalize_kernel(const float* __restrict__ beta_a,
                                                      const float* __restrict__ beta_v,
                                                      float inv_temp, int is_final,
                                                      float* __restrict__ out) {
    __shared__ float sums[36];
    const int o = blockIdx.x, b = blockIdx.y, t = threadIdx.x;
    if (t < 33) {
        const size_t base = (size_t)(b * OO + o) * NBLK * 36;
        float s = 0.f;
#pragma unroll
        for (int k = 0; k < NBLK; k++) s += g_partials[base + k * 36 + t];
        sums[t] = s;
    }
    __syncthreads();
    if (t < 16) {
        float S0 = sums[32];
        float S1 = sums[t], S2 = sums[16 + t];
        float inv = 1.f / (S0 + EPSV);
        float mean = S1 * inv;
        float raw = S2 - mean * (2.f * S1 - mean * S0);  // == sum rp*(v-mean)^2 exactly
        float var = fmaxf(raw * inv, 0.f) + EPSV;
        float lv = logf(var);
        float lvs = lv;
        for (int off = 8; off; off >>= 1) lvs += __shfl_down_sync(0x0000ffffu, lvs, off);
        if (is_final) {
            out[((size_t)b * OO + o) * 16 + t] = mean;
        } else {
            g_params[(b * OO + o) * 40 + t] = mean;
            g_params[(b * OO + o) * 40 + 16 + t] = 0.5f / var;
        }
        if (t == 0) {
            float bv = beta_v[o], ba = beta_a[o];
            float cost = S0 * fmaf(0.5f, lvs, 16.f * bv);
            float actj = 1.f / (1.f + expf(-inv_temp * (ba - cost)));
            if (is_final) {
                out[(size_t)BB * OO * 16 + b * OO + o] = actj;
            } else {
                // K0 = log(act+eps) - 0.5*sum_h log(2*pi*var_h)
                g_params[(b * OO + o) * 40 + 32] =
                    logf(actj + EPSV) - 0.5f * (16.f * 1.8378770664093453f + lvs);
            }
        }
    }
}

extern "C" void kernel_launch(void* const* d_in, const int* in_sizes, int n_in,
                              void* d_out, int out_size) {
    const float* pose = (const float*)d_in[0];
    const float* act  = (const float*)d_in[1];
    const float* w    = (const float*)d_in[2];
    const float* ba   = (const float*)d_in[3];
    const float* bv   = (const float*)d_in[4];
    float* out = (float*)d_out;

    dim3 gp(NBLK, BB);
    dim3 gf(OO, BB);
    em_pass_kernel<true><<<gp, 256>>>(pose, act, w);
    finalize_kernel<<<gf, 64>>>(ba, bv, 0.0005f, 0, out);
    em_pass_kernel<false><<<gp, 256>>>(pose, act, w);
    finalize_kernel<<<gf, 64>>>(ba, bv, 0.000975f, 0, out);
    em_pass_kernel<false><<<gp, 256>>>(pose, act, w);
    finalize_kernel<<<gf, 64>>>(ba, bv, 0.00142625f, 1, out);
}